// round 12
// baseline (speedup 1.0000x reference)
#include <cuda_runtime.h>
#include <cuda_fp16.h>
#include <math.h>
#include <stdint.h>

// Problem constants
#define BATCH   8
#define HH      64
#define WW_     64
#define DIM     512
#define NHEAD   16
#define DK      32
#define WS      8
#define SHIFT   4
#define LAYERS  4
#define NTOK    (BATCH * HH * WW_)          // 32768
#define TBL     225                          // (2*WS-1)^2
#define QKVN    (3 * DIM)                    // 1536

// ---------------- scratch (device globals; no allocation allowed) ----------
__device__ float  g_x   [NTOK * DIM];        // running state (f32)
__device__ __half g_xn  [NTOK * DIM];        // layernorm out (fp16)
__device__ __half g_qkv [NTOK * QKVN];       // Q|K|V (fp16)
__device__ __half g_at  [NTOK * DIM];        // attn out (fp16)
__device__ __half g_h   [NTOK * 4 * DIM];    // MLP hidden (fp16)
// transposed fp16 weights, [N, K] row-major
__device__ __half g_wqkvT[LAYERS * QKVN * DIM];   // rows: 0-511 Wq, 512-1535 Wkv
__device__ float  g_bqkv [LAYERS * QKVN];
__device__ __half g_woT [LAYERS * DIM * DIM];
__device__ __half g_w1T [LAYERS * 4 * DIM * DIM];
__device__ __half g_w2T [LAYERS * DIM * 4 * DIM];

// ---------------- helpers ----------------------------------------------------
__device__ __forceinline__ uint32_t smem_u32(const void* p) {
    uint32_t a;
    asm("{ .reg .u64 t; cvta.to.shared.u64 t, %1; cvt.u32.u64 %0, t; }"
        : "=r"(a) : "l"(p));
    return a;
}

__device__ __forceinline__ void mma_f16(
    float* c, const uint32_t* a, uint32_t b0, uint32_t b1)
{
    asm volatile(
        "mma.sync.aligned.m16n8k16.row.col.f32.f16.f16.f32 "
        "{%0,%1,%2,%3}, {%4,%5,%6,%7}, {%8,%9}, {%0,%1,%2,%3};\n"
        : "+f"(c[0]), "+f"(c[1]), "+f"(c[2]), "+f"(c[3])
        : "r"(a[0]), "r"(a[1]), "r"(a[2]), "r"(a[3]), "r"(b0), "r"(b1));
}

__device__ __forceinline__ void ldmx4(uint32_t* r, uint32_t addr) {
    asm volatile(
        "ldmatrix.sync.aligned.m8n8.x4.shared.b16 {%0,%1,%2,%3}, [%4];"
        : "=r"(r[0]), "=r"(r[1]), "=r"(r[2]), "=r"(r[3]) : "r"(addr));
}

// ---------------- weight transpose + fp16 convert ----------------------------
// in: W [K, N] f32 row-major -> out: Wt [N, K] fp16
__global__ __launch_bounds__(256) void wt_prep(
    const float* __restrict__ W, __half* __restrict__ Wt, int K, int N)
{
    __shared__ float t[32][33];
    int n0 = blockIdx.x * 32, k0 = blockIdx.y * 32;
    int tx = threadIdx.x, ty = threadIdx.y;   // 32 x 8
#pragma unroll
    for (int i = 0; i < 4; i++)
        t[ty + i * 8][tx] = W[(size_t)(k0 + ty + i * 8) * N + n0 + tx];
    __syncthreads();
#pragma unroll
    for (int i = 0; i < 4; i++)
        Wt[(size_t)(n0 + ty + i * 8) * K + k0 + tx] =
            __float2half_rn(t[tx][ty + i * 8]);
}

// concat bq|bkv per layer into g_bqkv
__global__ void bias_prep(const float* __restrict__ bq,
                          const float* __restrict__ bkv,
                          float* __restrict__ out)
{
    int l = blockIdx.x;
    for (int j = threadIdx.x; j < QKVN; j += blockDim.x)
        out[l * QKVN + j] = (j < DIM) ? bq[l * DIM + j]
                                      : bkv[l * 2 * DIM + (j - DIM)];
}

// ---------------- LayerNorm (fp16 output) ------------------------------------
__global__ __launch_bounds__(128) void ln_kernel(
    const float* __restrict__ x, const float* __restrict__ g,
    const float* __restrict__ b, __half* __restrict__ y)
{
    int tok = blockIdx.x;
    const float4* xp = reinterpret_cast<const float4*>(x + (size_t)tok * DIM);
    int tid = threadIdx.x;

    float4 v = xp[tid];
    float s = v.x + v.y + v.z + v.w;

    __shared__ float red1[4], red2[4];
#pragma unroll
    for (int o = 16; o > 0; o >>= 1) s += __shfl_xor_sync(0xffffffffu, s, o);
    if ((tid & 31) == 0) red1[tid >> 5] = s;
    __syncthreads();
    float mean = (red1[0] + red1[1] + red1[2] + red1[3]) * (1.f / DIM);

    float dx = v.x - mean, dy = v.y - mean, dz = v.z - mean, dw = v.w - mean;
    float s2 = dx * dx + dy * dy + dz * dz + dw * dw;
#pragma unroll
    for (int o = 16; o > 0; o >>= 1) s2 += __shfl_xor_sync(0xffffffffu, s2, o);
    if ((tid & 31) == 0) red2[tid >> 5] = s2;
    __syncthreads();
    float var  = (red2[0] + red2[1] + red2[2] + red2[3]) * (1.f / DIM);
    float rstd = rsqrtf(var + 1e-5f);

    int c = tid * 4;
    float4 gg = reinterpret_cast<const float4*>(g)[tid];
    float4 bb = reinterpret_cast<const float4*>(b)[tid];
    float r0 = dx * rstd * gg.x + bb.x;
    float r1 = dy * rstd * gg.y + bb.y;
    float r2 = dz * rstd * gg.z + bb.z;
    float r3 = dw * rstd * gg.w + bb.w;
    __half2* yp2 = reinterpret_cast<__half2*>(y + (size_t)tok * DIM + c);
    yp2[0] = __floats2half2_rn(r0, r1);
    yp2[1] = __floats2half2_rn(r2, r3);
}

// ---------------- tensor-core fp16 GEMM --------------------------------------
// C[M,N] = A[M,K] @ Wt[N,K]^T + bias; epi: bias(fp16) / res-add(f32) / gelu(fp16)
// CTA 256x128, BK=64, 512 threads (16 warps, warp tile 32x64), 3-stage cp.async.
#define EPI_BIAS 0
#define EPI_RES  1
#define EPI_GELU 2

#define RSB    144                              // smem row stride bytes (64h + pad)
#define ATILE  (256 * RSB)                      // 36864 B
#define BTILE  (128 * RSB)                      // 18432 B
#define STAGEB (ATILE + BTILE)                  // 55296 B
#define GEMM_SMEM (3 * STAGEB)                  // 165888 B

__global__ __launch_bounds__(512, 1) void gemm_tc(
    const __half* __restrict__ A, const __half* __restrict__ Wt,
    const float* __restrict__ bias, const float* __restrict__ res,
    void* __restrict__ outP, int N, int K, int epi)
{
    extern __shared__ char smem[];
    uint32_t sbase = smem_u32(smem);

    int tid = threadIdx.x;
    int wid = tid >> 5, lane = tid & 31;
    int gq = lane >> 2, tq = lane & 3;
    int wm = wid >> 1, wn = wid & 1;           // warp: rows wm*32, cols wn*64
    int bn = blockIdx.x * 128, bm = blockIdx.y * 256;

    // ldmatrix lane offsets (bytes within stage)
    int t8 = lane >> 3, l8 = lane & 7;
    uint32_t a_off = (uint32_t)((wm * 32 + (t8 & 1) * 8 + l8) * RSB
                                + (t8 >> 1) * 16);
    uint32_t b_off = (uint32_t)(ATILE + (wn * 64 + (t8 >> 1) * 8 + l8) * RSB
                                + (t8 & 1) * 16);

    float acc[2][8][4];
#pragma unroll
    for (int mt = 0; mt < 2; mt++)
#pragma unroll
        for (int nt = 0; nt < 8; nt++)
#pragma unroll
            for (int r = 0; r < 4; r++) acc[mt][nt][r] = 0.f;

    const int NKB = K >> 6;                     // BK = 64

    // loader: A 256 rows x 8 chunks(16B), B 128 rows x 8 chunks
    int l_row = tid >> 3, l_c = tid & 7;        // base row 0..63, chunk 0..7

#define LOAD_STAGE(kb, stg) do {                                               \
    uint32_t sS = sbase + (uint32_t)(stg) * STAGEB;                            \
    const __half* gA = A  + (size_t)(bm + l_row) * K + (kb) * 64 + l_c * 8;    \
    const __half* gB = Wt + (size_t)(bn + l_row) * K + (kb) * 64 + l_c * 8;    \
    uint32_t dof = (uint32_t)(l_row * RSB + l_c * 16);                         \
    _Pragma("unroll")                                                          \
    for (int i = 0; i < 4; i++)                                                \
        asm volatile("cp.async.cg.shared.global [%0], [%1], 16;"               \
            :: "r"(sS + dof + i * 64 * RSB), "l"(gA + (size_t)i * 64 * K));    \
    _Pragma("unroll")                                                          \
    for (int i = 0; i < 2; i++)                                                \
        asm volatile("cp.async.cg.shared.global [%0], [%1], 16;"               \
            :: "r"(sS + ATILE + dof + i * 64 * RSB),                           \
               "l"(gB + (size_t)i * 64 * K));                                  \
} while (0)

    LOAD_STAGE(0, 0);
    asm volatile("cp.async.commit_group;");
    LOAD_STAGE(1, 1);
    asm volatile("cp.async.commit_group;");

    int stg = 0;
    for (int kb = 0; kb < NKB; kb++) {
        if (kb == NKB - 1) asm volatile("cp.async.wait_group 0;");
        else               asm volatile("cp.async.wait_group 1;");
        __syncthreads();
        if (kb + 2 < NKB) {
            int ns = stg + 2; if (ns >= 3) ns -= 3;
            LOAD_STAGE(kb + 2, ns);
            asm volatile("cp.async.commit_group;");
        }
        uint32_t sS = sbase + (uint32_t)stg * STAGEB;
#pragma unroll
        for (int ks = 0; ks < 4; ks++) {
            uint32_t af[2][4];
            ldmx4(af[0], sS + a_off + ks * 32);
            ldmx4(af[1], sS + a_off + ks * 32 + 16 * RSB);
            uint32_t bf[4][4];
#pragma unroll
            for (int p = 0; p < 4; p++)
                ldmx4(bf[p], sS + b_off + ks * 32 + p * 16 * RSB);
#pragma unroll
            for (int p = 0; p < 4; p++) {
                mma_f16(acc[0][2 * p],     af[0], bf[p][0], bf[p][1]);
                mma_f16(acc[1][2 * p],     af[1], bf[p][0], bf[p][1]);
                mma_f16(acc[0][2 * p + 1], af[0], bf[p][2], bf[p][3]);
                mma_f16(acc[1][2 * p + 1], af[1], bf[p][2], bf[p][3]);
            }
        }
        if (++stg == 3) stg = 0;
    }

    // ---- epilogue ----------------------------------------------------------
    float*  outF = reinterpret_cast<float*>(outP);
    __half* outH = reinterpret_cast<__half*>(outP);
#pragma unroll
    for (int mt = 0; mt < 2; mt++) {
        int row0 = bm + wm * 32 + mt * 16 + gq;
        int row1 = row0 + 8;
#pragma unroll
        for (int nt = 0; nt < 8; nt++) {
            int col = bn + wn * 64 + nt * 8 + 2 * tq;
            float2 bc = *reinterpret_cast<const float2*>(bias + col);
            float v00 = acc[mt][nt][0] + bc.x;
            float v01 = acc[mt][nt][1] + bc.y;
            float v10 = acc[mt][nt][2] + bc.x;
            float v11 = acc[mt][nt][3] + bc.y;
            if (epi == EPI_RES) {
                float2 r0 = *reinterpret_cast<const float2*>(
                    res + (size_t)row0 * N + col);
                float2 r1 = *reinterpret_cast<const float2*>(
                    res + (size_t)row1 * N + col);
                *reinterpret_cast<float2*>(outF + (size_t)row0 * N + col) =
                    make_float2(v00 + r0.x, v01 + r0.y);
                *reinterpret_cast<float2*>(outF + (size_t)row1 * N + col) =
                    make_float2(v10 + r1.x, v11 + r1.y);
            } else if (epi == EPI_GELU) {
                const float K0 = 0.7978845608028654f, K1 = 0.044715f;
                v00 = 0.5f * v00 * (1.f + tanhf(K0 * (v00 + K1 * v00 * v00 * v00)));
                v01 = 0.5f * v01 * (1.f + tanhf(K0 * (v01 + K1 * v01 * v01 * v01)));
                v10 = 0.5f * v10 * (1.f + tanhf(K0 * (v10 + K1 * v10 * v10 * v10)));
                v11 = 0.5f * v11 * (1.f + tanhf(K0 * (v11 + K1 * v11 * v11 * v11)));
                *reinterpret_cast<__half2*>(outH + (size_t)row0 * N + col) =
                    __floats2half2_rn(v00, v01);
                *reinterpret_cast<__half2*>(outH + (size_t)row1 * N + col) =
                    __floats2half2_rn(v10, v11);
            } else {
                *reinterpret_cast<__half2*>(outH + (size_t)row0 * N + col) =
                    __floats2half2_rn(v00, v01);
                *reinterpret_cast<__half2*>(outH + (size_t)row1 * N + col) =
                    __floats2half2_rn(v10, v11);
            }
        }
    }
}

// ---------------- Windowed attention ------------------------------------------
// Single-pass softmax (shift-invariant; no max subtraction, overflow-clamped).
// No indexed register arrays -> no local-memory spills.
__global__ __launch_bounds__(64) void attn_kernel(
    const __half* __restrict__ qkv,
    const float* __restrict__ table, __half* __restrict__ out)
{
    __shared__ float Ks[64][DK];
    __shared__ float Vs[64][DK];
    __shared__ float tbl[TBL];
    __shared__ int   cnts[64];

    int w    = blockIdx.x;
    int head = blockIdx.y;
    int b  = w >> 6;
    int wi = w & 63;
    int wh = wi >> 3, wwc = wi & 7;
    int e  = threadIdx.x;
    int r  = e >> 3, c = e & 7;

    int gh = (wh * 8 + r + SHIFT) & 63;
    int gw = (wwc * 8 + c + SHIFT) & 63;
    int tok = (b * 64 + gh) * 64 + gw;

    const __half2* qp2 = reinterpret_cast<const __half2*>(
        qkv + (size_t)tok * QKVN + head * DK);
    const __half2* kp2 = qp2 + DIM / 2;
    const __half2* vp2 = qp2 + DIM;

    float qf[DK];
#pragma unroll
    for (int j = 0; j < DK / 2; j++) {
        float2 fq = __half22float2(qp2[j]);
        float2 fk = __half22float2(kp2[j]);
        float2 fv = __half22float2(vp2[j]);
        qf[2 * j] = fq.x;  qf[2 * j + 1] = fq.y;
        Ks[e][2 * j] = fk.x;  Ks[e][2 * j + 1] = fk.y;
        Vs[e][2 * j] = fv.x;  Vs[e][2 * j + 1] = fv.y;
    }
    int ii = wh * 8 + r, jj = wwc * 8 + c;
    int ridi = (ii < HH - WS) ? 0 : ((ii < HH - SHIFT) ? 1 : 2);
    int ridj = (jj < WW_ - WS) ? 0 : ((jj < WW_ - SHIFT) ? 1 : 2);
    cnts[e] = ridi * 3 + ridj;
    for (int t = e; t < TBL; t += 64) tbl[t] = table[t * NHEAD + head];
    __syncthreads();

    const float SCALE = 0.17677669529663687f;  // 1/sqrt(32)
    float o[DK];
#pragma unroll
    for (int j = 0; j < DK; j++) o[j] = 0.f;
    float sum = 0.f;
    int mycnt = cnts[e];
    int tb = (r + 7) * 15 + (c + 7);           // table base for this query

#pragma unroll 8
    for (int kk = 0; kk < 64; kk++) {
        const float4* kp4 = reinterpret_cast<const float4*>(Ks[kk]);
        float acc = 0.f;
#pragma unroll
        for (int j = 0; j < DK / 4; j++) {
            float4 k4 = kp4[j];
            acc = fmaf(qf[4 * j],     k4.x, acc);
            acc = fmaf(qf[4 * j + 1], k4.y, acc);
            acc = fmaf(qf[4 * j + 2], k4.z, acc);
            acc = fmaf(qf[4 * j + 3], k4.w, acc);
        }
        int kr = kk >> 3, kc = kk & 7;
        float sc = fmaf(acc, SCALE, tbl[tb - kr * 15 - kc]);
        float p = (mycnt == cnts[kk]) ? __expf(fminf(sc, 80.f)) : 0.f;
        sum += p;
        const float4* vp4 = reinterpret_cast<const float4*>(Vs[kk]);
#pragma unroll
        for (int j = 0; j < DK / 4; j++) {
            float4 v4 = vp4[j];
            o[4 * j]     = fmaf(p, v4.x, o[4 * j]);
            o[4 * j + 1] = fmaf(p, v4.y, o[4 * j + 1]);
            o[4 * j + 2] = fmaf(p, v4.z, o[4 * j + 2]);
            o[4 * j + 3] = fmaf(p, v4.w, o[4 * j + 3]);
        }
    }
    float inv = 1.f / sum;

    __half2* op2 = reinterpret_cast<__half2*>(
        out + (size_t)tok * DIM + head * DK);
#pragma unroll
    for (int j = 0; j < DK / 2; j++)
        op2[j] = __floats2half2_rn(o[2 * j] * inv, o[2 * j + 1] * inv);
}

// ---------------- launch ----------------------------------------------------
extern "C" void kernel_launch(void* const* d_in, const int* in_sizes, int n_in,
                              void* d_out, int out_size)
{
    const float* x_in  = (const float*)d_in[0];
    const float* Wq   = (const float*)d_in[3];
    const float* bq   = (const float*)d_in[4];
    const float* Wkv  = (const float*)d_in[5];
    const float* bkv  = (const float*)d_in[6];
    const float* Wo   = (const float*)d_in[7];
    const float* bo   = (const float*)d_in[8];
    const float* rtab = (const float*)d_in[9];
    const float* ln1g = (const float*)d_in[10];
    const float* ln1b = (const float*)d_in[11];
    const float* ln2g = (const float*)d_in[12];
    const float* ln2b = (const float*)d_in[13];
    const float* W1   = (const float*)d_in[14];
    const float* b1   = (const float*)d_in[15];
    const float* W2   = (const float*)d_in[16];
    const float* b2   = (const float*)d_in[17];

    float *gx, *gbqkv;
    __half *gxn, *gqkv, *gat, *ghid;
    __half *wqkvT, *woT, *w1T, *w2T;
    cudaGetSymbolAddress((void**)&gx,    g_x);
    cudaGetSymbolAddress((void**)&gxn,   g_xn);
    cudaGetSymbolAddress((void**)&gqkv,  g_qkv);
    cudaGetSymbolAddress((void**)&gat,   g_at);
    cudaGetSymbolAddress((void**)&ghid,  g_h);
    cudaGetSymbolAddress((void**)&wqkvT, g_wqkvT);
    cudaGetSymbolAddress((void**)&gbqkv, g_bqkv);
    cudaGetSymbolAddress((void**)&woT,   g_woT);
    cudaGetSymbolAddress((void**)&w1T,   g_w1T);
    cudaGetSymbolAddress((void**)&w2T,   g_w2T);

    cudaFuncSetAttribute(gemm_tc,
        cudaFuncAttributeMaxDynamicSharedMemorySize, GEMM_SMEM);

    // weight transposes (fp16) + fused qkv bias
    dim3 tb(32, 8);
    bias_prep<<<LAYERS, 512>>>(bq, bkv, gbqkv);
    for (int i = 0; i < LAYERS; i++) {
        __half* wqkvT_i = wqkvT + (size_t)i * QKVN * DIM;
        wt_prep<<<dim3(16, 16), tb>>>(Wq  + (size_t)i*DIM*DIM,   wqkvT_i,                DIM, DIM);
        wt_prep<<<dim3(32, 16), tb>>>(Wkv + (size_t)i*DIM*2*DIM, wqkvT_i + (size_t)DIM*DIM, DIM, 2*DIM);
        wt_prep<<<dim3(16, 16), tb>>>(Wo  + (size_t)i*DIM*DIM,   woT + (size_t)i*DIM*DIM,   DIM, DIM);
        wt_prep<<<dim3(64, 16), tb>>>(W1  + (size_t)i*DIM*4*DIM, w1T + (size_t)i*4*DIM*DIM, DIM, 4*DIM);
        wt_prep<<<dim3(16, 64), tb>>>(W2  + (size_t)i*4*DIM*DIM, w2T + (size_t)i*DIM*4*DIM, 4*DIM, DIM);
    }

    for (int i = 0; i < LAYERS; i++) {
        const float* cur_x = (i == 0) ? x_in : gx;       // residual stream in
        // LN1
        ln_kernel<<<NTOK, 128>>>(cur_x, ln1g + i * DIM, ln1b + i * DIM, gxn);
        // QKV = xn @ [Wq|Wkv] + [bq|bkv]   (fused, N=1536)
        gemm_tc<<<dim3(QKVN/128, NTOK/256), 512, GEMM_SMEM>>>(
            gxn, wqkvT + (size_t)i*QKVN*DIM, gbqkv + i*QKVN, nullptr, gqkv,
            QKVN, DIM, EPI_BIAS);
        // windowed attention
        attn_kernel<<<dim3(BATCH * 64, NHEAD), 64>>>(
            gqkv, rtab + (size_t)i * TBL * NHEAD, gat);
        // x = res + attn @ Wo + bo
        gemm_tc<<<dim3(DIM/128, NTOK/256), 512, GEMM_SMEM>>>(
            gat, woT + (size_t)i*DIM*DIM, bo + i*DIM, cur_x, gx,
            DIM, DIM, EPI_RES);
        // LN2
        ln_kernel<<<NTOK, 128>>>(gx, ln2g + i * DIM, ln2b + i * DIM, gxn);
        // h = gelu(xn @ W1 + b1)
        gemm_tc<<<dim3(4*DIM/128, NTOK/256), 512, GEMM_SMEM>>>(
            gxn, w1T + (size_t)i*4*DIM*DIM, b1 + i*4*DIM, nullptr, ghid,
            4*DIM, DIM, EPI_GELU);
        // x = x + h @ W2 + b2   (last layer writes d_out directly)
        float* outx = (i == LAYERS - 1) ? (float*)d_out : gx;
        gemm_tc<<<dim3(DIM/128, NTOK/256), 512, GEMM_SMEM>>>(
            ghid, w2T + (size_t)i*DIM*4*DIM, b2 + i*DIM, gx, outx,
            DIM, 4*DIM, EPI_RES);
    }
}

// round 13
// speedup vs baseline: 1.5240x; 1.5240x over previous
#include <cuda_runtime.h>
#include <cuda_fp16.h>
#include <math.h>
#include <stdint.h>

// Problem constants
#define BATCH   8
#define HH      64
#define WW_     64
#define DIM     512
#define NHEAD   16
#define DK      32
#define WS      8
#define SHIFT   4
#define LAYERS  4
#define NTOK    (BATCH * HH * WW_)          // 32768
#define TBL     225                          // (2*WS-1)^2
#define QKVN    (3 * DIM)                    // 1536

// ---------------- scratch (device globals; no allocation allowed) ----------
__device__ float  g_x   [NTOK * DIM];        // running state (f32)
__device__ __half g_xn  [NTOK * DIM];        // layernorm out (fp16)
__device__ __half g_qkv [NTOK * QKVN];       // Q|K|V (fp16)
__device__ __half g_at  [NTOK * DIM];        // attn out (fp16)
__device__ __half g_h   [NTOK * 4 * DIM];    // MLP hidden (fp16)
// transposed fp16 weights, [N, K] row-major
__device__ __half g_wqkvT[LAYERS * QKVN * DIM];   // rows: 0-511 Wq, 512-1535 Wkv
__device__ float  g_bqkv [LAYERS * QKVN];
__device__ __half g_woT [LAYERS * DIM * DIM];
__device__ __half g_w1T [LAYERS * 4 * DIM * DIM];
__device__ __half g_w2T [LAYERS * DIM * 4 * DIM];

// ---------------- helpers ----------------------------------------------------
__device__ __forceinline__ uint32_t smem_u32(const void* p) {
    uint32_t a;
    asm("{ .reg .u64 t; cvta.to.shared.u64 t, %1; cvt.u32.u64 %0, t; }"
        : "=r"(a) : "l"(p));
    return a;
}

__device__ __forceinline__ void mma_f16(
    float* c, const uint32_t* a, uint32_t b0, uint32_t b1)
{
    asm volatile(
        "mma.sync.aligned.m16n8k16.row.col.f32.f16.f16.f32 "
        "{%0,%1,%2,%3}, {%4,%5,%6,%7}, {%8,%9}, {%0,%1,%2,%3};\n"
        : "+f"(c[0]), "+f"(c[1]), "+f"(c[2]), "+f"(c[3])
        : "r"(a[0]), "r"(a[1]), "r"(a[2]), "r"(a[3]), "r"(b0), "r"(b1));
}

__device__ __forceinline__ void ldmx4(uint32_t* r, uint32_t addr) {
    asm volatile(
        "ldmatrix.sync.aligned.m8n8.x4.shared.b16 {%0,%1,%2,%3}, [%4];"
        : "=r"(r[0]), "=r"(r[1]), "=r"(r[2]), "=r"(r[3]) : "r"(addr));
}

// ---------------- weight transpose + fp16 convert ----------------------------
// in: W [K, N] f32 row-major -> out: Wt [N, K] fp16
__global__ __launch_bounds__(256) void wt_prep(
    const float* __restrict__ W, __half* __restrict__ Wt, int K, int N)
{
    __shared__ float t[32][33];
    int n0 = blockIdx.x * 32, k0 = blockIdx.y * 32;
    int tx = threadIdx.x, ty = threadIdx.y;   // 32 x 8
#pragma unroll
    for (int i = 0; i < 4; i++)
        t[ty + i * 8][tx] = W[(size_t)(k0 + ty + i * 8) * N + n0 + tx];
    __syncthreads();
#pragma unroll
    for (int i = 0; i < 4; i++)
        Wt[(size_t)(n0 + ty + i * 8) * K + k0 + tx] =
            __float2half_rn(t[tx][ty + i * 8]);
}

// concat bq|bkv per layer into g_bqkv
__global__ void bias_prep(const float* __restrict__ bq,
                          const float* __restrict__ bkv,
                          float* __restrict__ out)
{
    int l = blockIdx.x;
    for (int j = threadIdx.x; j < QKVN; j += blockDim.x)
        out[l * QKVN + j] = (j < DIM) ? bq[l * DIM + j]
                                      : bkv[l * 2 * DIM + (j - DIM)];
}

// ---------------- LayerNorm (fp16 output) ------------------------------------
__global__ __launch_bounds__(128) void ln_kernel(
    const float* __restrict__ x, const float* __restrict__ g,
    const float* __restrict__ b, __half* __restrict__ y)
{
    int tok = blockIdx.x;
    const float4* xp = reinterpret_cast<const float4*>(x + (size_t)tok * DIM);
    int tid = threadIdx.x;

    float4 v = xp[tid];
    float s = v.x + v.y + v.z + v.w;

    __shared__ float red1[4], red2[4];
#pragma unroll
    for (int o = 16; o > 0; o >>= 1) s += __shfl_xor_sync(0xffffffffu, s, o);
    if ((tid & 31) == 0) red1[tid >> 5] = s;
    __syncthreads();
    float mean = (red1[0] + red1[1] + red1[2] + red1[3]) * (1.f / DIM);

    float dx = v.x - mean, dy = v.y - mean, dz = v.z - mean, dw = v.w - mean;
    float s2 = dx * dx + dy * dy + dz * dz + dw * dw;
#pragma unroll
    for (int o = 16; o > 0; o >>= 1) s2 += __shfl_xor_sync(0xffffffffu, s2, o);
    if ((tid & 31) == 0) red2[tid >> 5] = s2;
    __syncthreads();
    float var  = (red2[0] + red2[1] + red2[2] + red2[3]) * (1.f / DIM);
    float rstd = rsqrtf(var + 1e-5f);

    int c = tid * 4;
    float4 gg = reinterpret_cast<const float4*>(g)[tid];
    float4 bb = reinterpret_cast<const float4*>(b)[tid];
    float r0 = dx * rstd * gg.x + bb.x;
    float r1 = dy * rstd * gg.y + bb.y;
    float r2 = dz * rstd * gg.z + bb.z;
    float r3 = dw * rstd * gg.w + bb.w;
    __half2* yp2 = reinterpret_cast<__half2*>(y + (size_t)tok * DIM + c);
    yp2[0] = __floats2half2_rn(r0, r1);
    yp2[1] = __floats2half2_rn(r2, r3);
}

// ---------------- tensor-core fp16 GEMM --------------------------------------
// C[M,N] = A[M,K] @ Wt[N,K]^T + bias; epi: bias(fp16) / res-add(f32) / gelu(fp16)
// CTA 256x128, BK=64, 512 threads (16 warps, warp tile 32x64), 3-stage cp.async.
#define EPI_BIAS 0
#define EPI_RES  1
#define EPI_GELU 2

#define RSB    144                              // smem row stride bytes (64h + pad)
#define ATILE  (256 * RSB)                      // 36864 B
#define BTILE  (128 * RSB)                      // 18432 B
#define STAGEB (ATILE + BTILE)                  // 55296 B
#define GEMM_SMEM (3 * STAGEB)                  // 165888 B

__global__ __launch_bounds__(512, 1) void gemm_tc(
    const __half* __restrict__ A, const __half* __restrict__ Wt,
    const float* __restrict__ bias, const float* __restrict__ res,
    void* __restrict__ outP, int N, int K, int epi)
{
    extern __shared__ char smem[];
    uint32_t sbase = smem_u32(smem);

    int tid = threadIdx.x;
    int wid = tid >> 5, lane = tid & 31;
    int gq = lane >> 2, tq = lane & 3;
    int wm = wid >> 1, wn = wid & 1;           // warp: rows wm*32, cols wn*64
    int bn = blockIdx.x * 128, bm = blockIdx.y * 256;

    // ldmatrix lane offsets (bytes within stage)
    int t8 = lane >> 3, l8 = lane & 7;
    uint32_t a_off = (uint32_t)((wm * 32 + (t8 & 1) * 8 + l8) * RSB
                                + (t8 >> 1) * 16);
    uint32_t b_off = (uint32_t)(ATILE + (wn * 64 + (t8 >> 1) * 8 + l8) * RSB
                                + (t8 & 1) * 16);

    float acc[2][8][4];
#pragma unroll
    for (int mt = 0; mt < 2; mt++)
#pragma unroll
        for (int nt = 0; nt < 8; nt++)
#pragma unroll
            for (int r = 0; r < 4; r++) acc[mt][nt][r] = 0.f;

    const int NKB = K >> 6;                     // BK = 64

    // loader: A 256 rows x 8 chunks(16B), B 128 rows x 8 chunks
    int l_row = tid >> 3, l_c = tid & 7;        // base row 0..63, chunk 0..7

#define LOAD_STAGE(kb, stg) do {                                               \
    uint32_t sS = sbase + (uint32_t)(stg) * STAGEB;                            \
    const __half* gA = A  + (size_t)(bm + l_row) * K + (kb) * 64 + l_c * 8;    \
    const __half* gB = Wt + (size_t)(bn + l_row) * K + (kb) * 64 + l_c * 8;    \
    uint32_t dof = (uint32_t)(l_row * RSB + l_c * 16);                         \
    _Pragma("unroll")                                                          \
    for (int i = 0; i < 4; i++)                                                \
        asm volatile("cp.async.cg.shared.global [%0], [%1], 16;"               \
            :: "r"(sS + dof + i * 64 * RSB), "l"(gA + (size_t)i * 64 * K));    \
    _Pragma("unroll")                                                          \
    for (int i = 0; i < 2; i++)                                                \
        asm volatile("cp.async.cg.shared.global [%0], [%1], 16;"               \
            :: "r"(sS + ATILE + dof + i * 64 * RSB),                           \
               "l"(gB + (size_t)i * 64 * K));                                  \
} while (0)

    LOAD_STAGE(0, 0);
    asm volatile("cp.async.commit_group;");
    LOAD_STAGE(1, 1);
    asm volatile("cp.async.commit_group;");

    int stg = 0;
    for (int kb = 0; kb < NKB; kb++) {
        if (kb == NKB - 1) asm volatile("cp.async.wait_group 0;");
        else               asm volatile("cp.async.wait_group 1;");
        __syncthreads();
        if (kb + 2 < NKB) {
            int ns = stg + 2; if (ns >= 3) ns -= 3;
            LOAD_STAGE(kb + 2, ns);
            asm volatile("cp.async.commit_group;");
        }
        uint32_t sS = sbase + (uint32_t)stg * STAGEB;
#pragma unroll
        for (int ks = 0; ks < 4; ks++) {
            uint32_t af[2][4];
            ldmx4(af[0], sS + a_off + ks * 32);
            ldmx4(af[1], sS + a_off + ks * 32 + 16 * RSB);
            uint32_t bf[4][4];
#pragma unroll
            for (int p = 0; p < 4; p++)
                ldmx4(bf[p], sS + b_off + ks * 32 + p * 16 * RSB);
#pragma unroll
            for (int p = 0; p < 4; p++) {
                mma_f16(acc[0][2 * p],     af[0], bf[p][0], bf[p][1]);
                mma_f16(acc[1][2 * p],     af[1], bf[p][0], bf[p][1]);
                mma_f16(acc[0][2 * p + 1], af[0], bf[p][2], bf[p][3]);
                mma_f16(acc[1][2 * p + 1], af[1], bf[p][2], bf[p][3]);
            }
        }
        if (++stg == 3) stg = 0;
    }

    // ---- epilogue ----------------------------------------------------------
    float*  outF = reinterpret_cast<float*>(outP);
    __half* outH = reinterpret_cast<__half*>(outP);
#pragma unroll
    for (int mt = 0; mt < 2; mt++) {
        int row0 = bm + wm * 32 + mt * 16 + gq;
        int row1 = row0 + 8;
#pragma unroll
        for (int nt = 0; nt < 8; nt++) {
            int col = bn + wn * 64 + nt * 8 + 2 * tq;
            float2 bc = *reinterpret_cast<const float2*>(bias + col);
            float v00 = acc[mt][nt][0] + bc.x;
            float v01 = acc[mt][nt][1] + bc.y;
            float v10 = acc[mt][nt][2] + bc.x;
            float v11 = acc[mt][nt][3] + bc.y;
            if (epi == EPI_RES) {
                float2 r0 = *reinterpret_cast<const float2*>(
                    res + (size_t)row0 * N + col);
                float2 r1 = *reinterpret_cast<const float2*>(
                    res + (size_t)row1 * N + col);
                *reinterpret_cast<float2*>(outF + (size_t)row0 * N + col) =
                    make_float2(v00 + r0.x, v01 + r0.y);
                *reinterpret_cast<float2*>(outF + (size_t)row1 * N + col) =
                    make_float2(v10 + r1.x, v11 + r1.y);
            } else if (epi == EPI_GELU) {
                const float K0 = 0.7978845608028654f, K1 = 0.044715f;
                v00 = 0.5f * v00 * (1.f + tanhf(K0 * (v00 + K1 * v00 * v00 * v00)));
                v01 = 0.5f * v01 * (1.f + tanhf(K0 * (v01 + K1 * v01 * v01 * v01)));
                v10 = 0.5f * v10 * (1.f + tanhf(K0 * (v10 + K1 * v10 * v10 * v10)));
                v11 = 0.5f * v11 * (1.f + tanhf(K0 * (v11 + K1 * v11 * v11 * v11)));
                *reinterpret_cast<__half2*>(outH + (size_t)row0 * N + col) =
                    __floats2half2_rn(v00, v01);
                *reinterpret_cast<__half2*>(outH + (size_t)row1 * N + col) =
                    __floats2half2_rn(v10, v11);
            } else {
                *reinterpret_cast<__half2*>(outH + (size_t)row0 * N + col) =
                    __floats2half2_rn(v00, v01);
                *reinterpret_cast<__half2*>(outH + (size_t)row1 * N + col) =
                    __floats2half2_rn(v10, v11);
            }
        }
    }
}

// ---------------- Windowed attention ------------------------------------------
// Two-pass softmax with p staged in SHARED memory (no local spills, no big
// unrolled live ranges). Shift-invariant softmax (no max subtraction; clamp).
__global__ __launch_bounds__(64) void attn_kernel(
    const __half* __restrict__ qkv,
    const float* __restrict__ table, __half* __restrict__ out)
{
    __shared__ float Ks[64][DK];       // 8 KB
    __shared__ float Vs[64][DK];       // 8 KB
    __shared__ float Ps[64][65];       // 16.25 KB (pad -> conflict-free cols)
    __shared__ float tbl[TBL];
    __shared__ int   cnts[64];

    int w    = blockIdx.x;
    int head = blockIdx.y;
    int b  = w >> 6;
    int wi = w & 63;
    int wh = wi >> 3, wwc = wi & 7;
    int e  = threadIdx.x;
    int r  = e >> 3, c = e & 7;

    int gh = (wh * 8 + r + SHIFT) & 63;
    int gw = (wwc * 8 + c + SHIFT) & 63;
    int tok = (b * 64 + gh) * 64 + gw;

    const __half2* qp2 = reinterpret_cast<const __half2*>(
        qkv + (size_t)tok * QKVN + head * DK);
    const __half2* kp2 = qp2 + DIM / 2;
    const __half2* vp2 = qp2 + DIM;

    float qf[DK];
#pragma unroll
    for (int j = 0; j < DK / 2; j++) {
        float2 fq = __half22float2(qp2[j]);
        float2 fk = __half22float2(kp2[j]);
        float2 fv = __half22float2(vp2[j]);
        qf[2 * j] = fq.x;  qf[2 * j + 1] = fq.y;
        Ks[e][2 * j] = fk.x;  Ks[e][2 * j + 1] = fk.y;
        Vs[e][2 * j] = fv.x;  Vs[e][2 * j + 1] = fv.y;
    }
    int ii = wh * 8 + r, jj = wwc * 8 + c;
    int ridi = (ii < HH - WS) ? 0 : ((ii < HH - SHIFT) ? 1 : 2);
    int ridj = (jj < WW_ - WS) ? 0 : ((jj < WW_ - SHIFT) ? 1 : 2);
    cnts[e] = ridi * 3 + ridj;
    for (int t = e; t < TBL; t += 64) tbl[t] = table[t * NHEAD + head];
    __syncthreads();

    const float SCALE = 0.17677669529663687f;  // 1/sqrt(32)
    int mycnt = cnts[e];
    int tb = (r + 7) * 15 + (c + 7);           // table base for this query

    // ---- pass 1: scores -> p in shared; only qf[] lives here ---------------
    float sum = 0.f;
#pragma unroll 4
    for (int kk = 0; kk < 64; kk++) {
        const float4* kp4 = reinterpret_cast<const float4*>(Ks[kk]);
        float acc = 0.f;
#pragma unroll
        for (int j = 0; j < DK / 4; j++) {
            float4 k4 = kp4[j];
            acc = fmaf(qf[4 * j],     k4.x, acc);
            acc = fmaf(qf[4 * j + 1], k4.y, acc);
            acc = fmaf(qf[4 * j + 2], k4.z, acc);
            acc = fmaf(qf[4 * j + 3], k4.w, acc);
        }
        int kr = kk >> 3, kc = kk & 7;
        float sc = fmaf(acc, SCALE, tbl[tb - kr * 15 - kc]);
        float p = (mycnt == cnts[kk]) ? __expf(fminf(sc, 80.f)) : 0.f;
        sum += p;
        Ps[e][kk] = p;
    }
    float inv = 1.f / sum;

    // ---- pass 2: weighted V; only o[] lives here ---------------------------
    float o[DK];
#pragma unroll
    for (int j = 0; j < DK; j++) o[j] = 0.f;
#pragma unroll 4
    for (int kk = 0; kk < 64; kk++) {
        float p = Ps[e][kk];
        const float4* vp4 = reinterpret_cast<const float4*>(Vs[kk]);
#pragma unroll
        for (int j = 0; j < DK / 4; j++) {
            float4 v4 = vp4[j];
            o[4 * j]     = fmaf(p, v4.x, o[4 * j]);
            o[4 * j + 1] = fmaf(p, v4.y, o[4 * j + 1]);
            o[4 * j + 2] = fmaf(p, v4.z, o[4 * j + 2]);
            o[4 * j + 3] = fmaf(p, v4.w, o[4 * j + 3]);
        }
    }

    __half2* op2 = reinterpret_cast<__half2*>(
        out + (size_t)tok * DIM + head * DK);
#pragma unroll
    for (int j = 0; j < DK / 2; j++)
        op2[j] = __floats2half2_rn(o[2 * j] * inv, o[2 * j + 1] * inv);
}

// ---------------- launch ----------------------------------------------------
extern "C" void kernel_launch(void* const* d_in, const int* in_sizes, int n_in,
                              void* d_out, int out_size)
{
    const float* x_in  = (const float*)d_in[0];
    const float* Wq   = (const float*)d_in[3];
    const float* bq   = (const float*)d_in[4];
    const float* Wkv  = (const float*)d_in[5];
    const float* bkv  = (const float*)d_in[6];
    const float* Wo   = (const float*)d_in[7];
    const float* bo   = (const float*)d_in[8];
    const float* rtab = (const float*)d_in[9];
    const float* ln1g = (const float*)d_in[10];
    const float* ln1b = (const float*)d_in[11];
    const float* ln2g = (const float*)d_in[12];
    const float* ln2b = (const float*)d_in[13];
    const float* W1   = (const float*)d_in[14];
    const float* b1   = (const float*)d_in[15];
    const float* W2   = (const float*)d_in[16];
    const float* b2   = (const float*)d_in[17];

    float *gx, *gbqkv;
    __half *gxn, *gqkv, *gat, *ghid;
    __half *wqkvT, *woT, *w1T, *w2T;
    cudaGetSymbolAddress((void**)&gx,    g_x);
    cudaGetSymbolAddress((void**)&gxn,   g_xn);
    cudaGetSymbolAddress((void**)&gqkv,  g_qkv);
    cudaGetSymbolAddress((void**)&gat,   g_at);
    cudaGetSymbolAddress((void**)&ghid,  g_h);
    cudaGetSymbolAddress((void**)&wqkvT, g_wqkvT);
    cudaGetSymbolAddress((void**)&gbqkv, g_bqkv);
    cudaGetSymbolAddress((void**)&woT,   g_woT);
    cudaGetSymbolAddress((void**)&w1T,   g_w1T);
    cudaGetSymbolAddress((void**)&w2T,   g_w2T);

    cudaFuncSetAttribute(gemm_tc,
        cudaFuncAttributeMaxDynamicSharedMemorySize, GEMM_SMEM);

    // weight transposes (fp16) + fused qkv bias
    dim3 tb(32, 8);
    bias_prep<<<LAYERS, 512>>>(bq, bkv, gbqkv);
    for (int i = 0; i < LAYERS; i++) {
        __half* wqkvT_i = wqkvT + (size_t)i * QKVN * DIM;
        wt_prep<<<dim3(16, 16), tb>>>(Wq  + (size_t)i*DIM*DIM,   wqkvT_i,                DIM, DIM);
        wt_prep<<<dim3(32, 16), tb>>>(Wkv + (size_t)i*DIM*2*DIM, wqkvT_i + (size_t)DIM*DIM, DIM, 2*DIM);
        wt_prep<<<dim3(16, 16), tb>>>(Wo  + (size_t)i*DIM*DIM,   woT + (size_t)i*DIM*DIM,   DIM, DIM);
        wt_prep<<<dim3(64, 16), tb>>>(W1  + (size_t)i*DIM*4*DIM, w1T + (size_t)i*4*DIM*DIM, DIM, 4*DIM);
        wt_prep<<<dim3(16, 64), tb>>>(W2  + (size_t)i*4*DIM*DIM, w2T + (size_t)i*DIM*4*DIM, 4*DIM, DIM);
    }

    for (int i = 0; i < LAYERS; i++) {
        const float* cur_x = (i == 0) ? x_in : gx;       // residual stream in
        // LN1
        ln_kernel<<<NTOK, 128>>>(cur_x, ln1g + i * DIM, ln1b + i * DIM, gxn);
        // QKV = xn @ [Wq|Wkv] + [bq|bkv]   (fused, N=1536)
        gemm_tc<<<dim3(QKVN/128, NTOK/256), 512, GEMM_SMEM>>>(
            gxn, wqkvT + (size_t)i*QKVN*DIM, gbqkv + i*QKVN, nullptr, gqkv,
            QKVN, DIM, EPI_BIAS);
        // windowed attention
        attn_kernel<<<dim3(BATCH * 64, NHEAD), 64>>>(
            gqkv, rtab + (size_t)i * TBL * NHEAD, gat);
        // x = res + attn @ Wo + bo
        gemm_tc<<<dim3(DIM/128, NTOK/256), 512, GEMM_SMEM>>>(
            gat, woT + (size_t)i*DIM*DIM, bo + i*DIM, cur_x, gx,
            DIM, DIM, EPI_RES);
        // LN2
        ln_kernel<<<NTOK, 128>>>(gx, ln2g + i * DIM, ln2b + i * DIM, gxn);
        // h = gelu(xn @ W1 + b1)
        gemm_tc<<<dim3(4*DIM/128, NTOK/256), 512, GEMM_SMEM>>>(
            gxn, w1T + (size_t)i*4*DIM*DIM, b1 + i*4*DIM, nullptr, ghid,
            4*DIM, DIM, EPI_GELU);
        // x = x + h @ W2 + b2   (last layer writes d_out directly)
        float* outx = (i == LAYERS - 1) ? (float*)d_out : gx;
        gemm_tc<<<dim3(DIM/128, NTOK/256), 512, GEMM_SMEM>>>(
            ghid, w2T + (size_t)i*DIM*4*DIM, b2 + i*DIM, gx, outx,
            DIM, 4*DIM, EPI_RES);
    }
}

// round 14
// speedup vs baseline: 1.6577x; 1.0877x over previous
#include <cuda_runtime.h>
#include <cuda_fp16.h>
#include <math.h>
#include <stdint.h>

// Problem constants
#define BATCH   8
#define HH      64
#define WW_     64
#define DIM     512
#define NHEAD   16
#define DK      32
#define WS      8
#define SHIFT   4
#define LAYERS  4
#define NTOK    (BATCH * HH * WW_)          // 32768
#define TBL     225                          // (2*WS-1)^2
#define QKVN    (3 * DIM)                    // 1536

// ---------------- scratch (device globals; no allocation allowed) ----------
__device__ float  g_x   [NTOK * DIM];        // running state (f32)
__device__ __half g_xn  [NTOK * DIM];        // layernorm out (fp16)
__device__ __half g_qkv [NTOK * QKVN];       // Q|K|V (fp16)
__device__ __half g_at  [NTOK * DIM];        // attn out (fp16)
__device__ __half g_h   [NTOK * 4 * DIM];    // MLP hidden (fp16)
// transposed fp16 weights, [N, K] row-major
__device__ __half g_wqkvT[LAYERS * QKVN * DIM];   // rows: 0-511 Wq, 512-1535 Wkv
__device__ float  g_bqkv [LAYERS * QKVN];
__device__ __half g_woT [LAYERS * DIM * DIM];
__device__ __half g_w1T [LAYERS * 4 * DIM * DIM];
__device__ __half g_w2T [LAYERS * DIM * 4 * DIM];

// ---------------- helpers ----------------------------------------------------
__device__ __forceinline__ uint32_t smem_u32(const void* p) {
    uint32_t a;
    asm("{ .reg .u64 t; cvta.to.shared.u64 t, %1; cvt.u32.u64 %0, t; }"
        : "=r"(a) : "l"(p));
    return a;
}

__device__ __forceinline__ void mma_f16(
    float* c, const uint32_t* a, uint32_t b0, uint32_t b1)
{
    asm volatile(
        "mma.sync.aligned.m16n8k16.row.col.f32.f16.f16.f32 "
        "{%0,%1,%2,%3}, {%4,%5,%6,%7}, {%8,%9}, {%0,%1,%2,%3};\n"
        : "+f"(c[0]), "+f"(c[1]), "+f"(c[2]), "+f"(c[3])
        : "r"(a[0]), "r"(a[1]), "r"(a[2]), "r"(a[3]), "r"(b0), "r"(b1));
}

__device__ __forceinline__ void ldmx4(uint32_t* r, uint32_t addr) {
    asm volatile(
        "ldmatrix.sync.aligned.m8n8.x4.shared.b16 {%0,%1,%2,%3}, [%4];"
        : "=r"(r[0]), "=r"(r[1]), "=r"(r[2]), "=r"(r[3]) : "r"(addr));
}

// ---------------- weight transpose + fp16 convert ----------------------------
// in: W [K, N] f32 row-major -> out: Wt [N, K] fp16; z = layer index.
__global__ __launch_bounds__(256) void wt_prep(
    const float* __restrict__ W0, __half* __restrict__ Wt0, int K, int N)
{
    const float* W  = W0  + (size_t)blockIdx.z * K * N;
    __half*      Wt = Wt0 + (size_t)blockIdx.z * K * N;
    __shared__ float t[32][33];
    int n0 = blockIdx.x * 32, k0 = blockIdx.y * 32;
    int tx = threadIdx.x, ty = threadIdx.y;   // 32 x 8
#pragma unroll
    for (int i = 0; i < 4; i++)
        t[ty + i * 8][tx] = W[(size_t)(k0 + ty + i * 8) * N + n0 + tx];
    __syncthreads();
#pragma unroll
    for (int i = 0; i < 4; i++)
        Wt[(size_t)(n0 + ty + i * 8) * K + k0 + tx] =
            __float2half_rn(t[tx][ty + i * 8]);
}

// qkv fused weight prep: write Wq rows [0,512) and Wkv rows [512,1536)
__global__ __launch_bounds__(256) void wt_prep_off(
    const float* __restrict__ W0, __half* __restrict__ Wt0, int K, int N,
    int rowOff, int strideW, int strideWt)
{
    const float* W  = W0  + (size_t)blockIdx.z * strideW;
    __half*      Wt = Wt0 + (size_t)blockIdx.z * strideWt + (size_t)rowOff * K;
    __shared__ float t[32][33];
    int n0 = blockIdx.x * 32, k0 = blockIdx.y * 32;
    int tx = threadIdx.x, ty = threadIdx.y;
#pragma unroll
    for (int i = 0; i < 4; i++)
        t[ty + i * 8][tx] = W[(size_t)(k0 + ty + i * 8) * N + n0 + tx];
    __syncthreads();
#pragma unroll
    for (int i = 0; i < 4; i++)
        Wt[(size_t)(n0 + ty + i * 8) * K + k0 + tx] =
            __float2half_rn(t[tx][ty + i * 8]);
}

// concat bq|bkv per layer into g_bqkv
__global__ void bias_prep(const float* __restrict__ bq,
                          const float* __restrict__ bkv,
                          float* __restrict__ out)
{
    int l = blockIdx.x;
    for (int j = threadIdx.x; j < QKVN; j += blockDim.x)
        out[l * QKVN + j] = (j < DIM) ? bq[l * DIM + j]
                                      : bkv[l * 2 * DIM + (j - DIM)];
}

// ---------------- LayerNorm (fp16 output) ------------------------------------
__global__ __launch_bounds__(128) void ln_kernel(
    const float* __restrict__ x, const float* __restrict__ g,
    const float* __restrict__ b, __half* __restrict__ y)
{
    int tok = blockIdx.x;
    const float4* xp = reinterpret_cast<const float4*>(x + (size_t)tok * DIM);
    int tid = threadIdx.x;

    float4 v = xp[tid];
    float s = v.x + v.y + v.z + v.w;

    __shared__ float red1[4], red2[4];
#pragma unroll
    for (int o = 16; o > 0; o >>= 1) s += __shfl_xor_sync(0xffffffffu, s, o);
    if ((tid & 31) == 0) red1[tid >> 5] = s;
    __syncthreads();
    float mean = (red1[0] + red1[1] + red1[2] + red1[3]) * (1.f / DIM);

    float dx = v.x - mean, dy = v.y - mean, dz = v.z - mean, dw = v.w - mean;
    float s2 = dx * dx + dy * dy + dz * dz + dw * dw;
#pragma unroll
    for (int o = 16; o > 0; o >>= 1) s2 += __shfl_xor_sync(0xffffffffu, s2, o);
    if ((tid & 31) == 0) red2[tid >> 5] = s2;
    __syncthreads();
    float var  = (red2[0] + red2[1] + red2[2] + red2[3]) * (1.f / DIM);
    float rstd = rsqrtf(var + 1e-5f);

    int c = tid * 4;
    float4 gg = reinterpret_cast<const float4*>(g)[tid];
    float4 bb = reinterpret_cast<const float4*>(b)[tid];
    float r0 = dx * rstd * gg.x + bb.x;
    float r1 = dy * rstd * gg.y + bb.y;
    float r2 = dz * rstd * gg.z + bb.z;
    float r3 = dw * rstd * gg.w + bb.w;
    __half2* yp2 = reinterpret_cast<__half2*>(y + (size_t)tok * DIM + c);
    yp2[0] = __floats2half2_rn(r0, r1);
    yp2[1] = __floats2half2_rn(r2, r3);
}

// ---------------- tensor-core fp16 GEMM --------------------------------------
// C[M,N] = A[M,K] @ Wt[N,K]^T + bias; epi: bias(fp16) / res-add(f32) / gelu(fp16)
// CTA 128x128, BK=64, 256 threads (8 warps, warp tile 32x64), 3-stage cp.async,
// 2 CTAs/SM so one CTA's mainloop hides the other's prologue/epilogue.
#define EPI_BIAS 0
#define EPI_RES  1
#define EPI_GELU 2

#define RSB    144                              // smem row stride bytes (64h + pad)
#define ATILE  (128 * RSB)                      // 18432 B
#define STAGEB (2 * ATILE)                      // 36864 B (A + B)
#define GEMM_SMEM (3 * STAGEB)                  // 110592 B

__global__ __launch_bounds__(256, 2) void gemm_tc(
    const __half* __restrict__ A, const __half* __restrict__ Wt,
    const float* __restrict__ bias, const float* __restrict__ res,
    void* __restrict__ outP, int N, int K, int epi)
{
    extern __shared__ char smem[];
    uint32_t sbase = smem_u32(smem);

    int tid = threadIdx.x;
    int wid = tid >> 5, lane = tid & 31;
    int gq = lane >> 2, tq = lane & 3;
    int wm = wid >> 1, wn = wid & 1;           // warp: rows wm*32, cols wn*64
    int bn = blockIdx.x * 128, bm = blockIdx.y * 128;

    // ldmatrix lane offsets (bytes within stage)
    int t8 = lane >> 3, l8 = lane & 7;
    uint32_t a_off = (uint32_t)((wm * 32 + (t8 & 1) * 8 + l8) * RSB
                                + (t8 >> 1) * 16);
    uint32_t b_off = (uint32_t)(ATILE + (wn * 64 + (t8 >> 1) * 8 + l8) * RSB
                                + (t8 & 1) * 16);

    float acc[2][8][4];
#pragma unroll
    for (int mt = 0; mt < 2; mt++)
#pragma unroll
        for (int nt = 0; nt < 8; nt++)
#pragma unroll
            for (int r = 0; r < 4; r++) acc[mt][nt][r] = 0.f;

    const int NKB = K >> 6;                     // BK = 64

    // loader: A 128 rows x 8 chunks(16B), B 128 rows x 8 chunks; 256 threads
    int l_row = tid >> 3, l_c = tid & 7;        // base row 0..31, chunk 0..7

#define LOAD_STAGE(kb, stg) do {                                               \
    uint32_t sS = sbase + (uint32_t)(stg) * STAGEB;                            \
    const __half* gA = A  + (size_t)(bm + l_row) * K + (kb) * 64 + l_c * 8;    \
    const __half* gB = Wt + (size_t)(bn + l_row) * K + (kb) * 64 + l_c * 8;    \
    uint32_t dof = (uint32_t)(l_row * RSB + l_c * 16);                         \
    _Pragma("unroll")                                                          \
    for (int i = 0; i < 4; i++)                                                \
        asm volatile("cp.async.cg.shared.global [%0], [%1], 16;"               \
            :: "r"(sS + dof + i * 32 * RSB), "l"(gA + (size_t)i * 32 * K));    \
    _Pragma("unroll")                                                          \
    for (int i = 0; i < 4; i++)                                                \
        asm volatile("cp.async.cg.shared.global [%0], [%1], 16;"               \
            :: "r"(sS + ATILE + dof + i * 32 * RSB),                           \
               "l"(gB + (size_t)i * 32 * K));                                  \
} while (0)

    LOAD_STAGE(0, 0);
    asm volatile("cp.async.commit_group;");
    LOAD_STAGE(1, 1);
    asm volatile("cp.async.commit_group;");

    int stg = 0;
    for (int kb = 0; kb < NKB; kb++) {
        if (kb == NKB - 1) asm volatile("cp.async.wait_group 0;");
        else               asm volatile("cp.async.wait_group 1;");
        __syncthreads();
        if (kb + 2 < NKB) {
            int ns = stg + 2; if (ns >= 3) ns -= 3;
            LOAD_STAGE(kb + 2, ns);
            asm volatile("cp.async.commit_group;");
        }
        uint32_t sS = sbase + (uint32_t)stg * STAGEB;
#pragma unroll
        for (int ks = 0; ks < 4; ks++) {
            uint32_t af[2][4];
            ldmx4(af[0], sS + a_off + ks * 32);
            ldmx4(af[1], sS + a_off + ks * 32 + 16 * RSB);
            uint32_t bf[4][4];
#pragma unroll
            for (int p = 0; p < 4; p++)
                ldmx4(bf[p], sS + b_off + ks * 32 + p * 16 * RSB);
#pragma unroll
            for (int p = 0; p < 4; p++) {
                mma_f16(acc[0][2 * p],     af[0], bf[p][0], bf[p][1]);
                mma_f16(acc[1][2 * p],     af[1], bf[p][0], bf[p][1]);
                mma_f16(acc[0][2 * p + 1], af[0], bf[p][2], bf[p][3]);
                mma_f16(acc[1][2 * p + 1], af[1], bf[p][2], bf[p][3]);
            }
        }
        if (++stg == 3) stg = 0;
    }

    // ---- epilogue ----------------------------------------------------------
    float*  outF = reinterpret_cast<float*>(outP);
    __half* outH = reinterpret_cast<__half*>(outP);
#pragma unroll
    for (int mt = 0; mt < 2; mt++) {
        int row0 = bm + wm * 32 + mt * 16 + gq;
        int row1 = row0 + 8;
#pragma unroll
        for (int nt = 0; nt < 8; nt++) {
            int col = bn + wn * 64 + nt * 8 + 2 * tq;
            float2 bc = *reinterpret_cast<const float2*>(bias + col);
            float v00 = acc[mt][nt][0] + bc.x;
            float v01 = acc[mt][nt][1] + bc.y;
            float v10 = acc[mt][nt][2] + bc.x;
            float v11 = acc[mt][nt][3] + bc.y;
            if (epi == EPI_RES) {
                float2 r0 = *reinterpret_cast<const float2*>(
                    res + (size_t)row0 * N + col);
                float2 r1 = *reinterpret_cast<const float2*>(
                    res + (size_t)row1 * N + col);
                *reinterpret_cast<float2*>(outF + (size_t)row0 * N + col) =
                    make_float2(v00 + r0.x, v01 + r0.y);
                *reinterpret_cast<float2*>(outF + (size_t)row1 * N + col) =
                    make_float2(v10 + r1.x, v11 + r1.y);
            } else if (epi == EPI_GELU) {
                const float K0 = 0.7978845608028654f, K1 = 0.044715f;
                v00 = 0.5f * v00 * (1.f + tanhf(K0 * (v00 + K1 * v00 * v00 * v00)));
                v01 = 0.5f * v01 * (1.f + tanhf(K0 * (v01 + K1 * v01 * v01 * v01)));
                v10 = 0.5f * v10 * (1.f + tanhf(K0 * (v10 + K1 * v10 * v10 * v10)));
                v11 = 0.5f * v11 * (1.f + tanhf(K0 * (v11 + K1 * v11 * v11 * v11)));
                *reinterpret_cast<__half2*>(outH + (size_t)row0 * N + col) =
                    __floats2half2_rn(v00, v01);
                *reinterpret_cast<__half2*>(outH + (size_t)row1 * N + col) =
                    __floats2half2_rn(v10, v11);
            } else {
                *reinterpret_cast<__half2*>(outH + (size_t)row0 * N + col) =
                    __floats2half2_rn(v00, v01);
                *reinterpret_cast<__half2*>(outH + (size_t)row1 * N + col) =
                    __floats2half2_rn(v10, v11);
            }
        }
    }
}

// ---------------- Windowed attention ------------------------------------------
// Two-pass softmax with p staged in SHARED memory (no local spills).
__global__ __launch_bounds__(64) void attn_kernel(
    const __half* __restrict__ qkv,
    const float* __restrict__ table, __half* __restrict__ out)
{
    __shared__ float Ks[64][DK];
    __shared__ float Vs[64][DK];
    __shared__ float Ps[64][65];
    __shared__ float tbl[TBL];
    __shared__ int   cnts[64];

    int w    = blockIdx.x;
    int head = blockIdx.y;
    int b  = w >> 6;
    int wi = w & 63;
    int wh = wi >> 3, wwc = wi & 7;
    int e  = threadIdx.x;
    int r  = e >> 3, c = e & 7;

    int gh = (wh * 8 + r + SHIFT) & 63;
    int gw = (wwc * 8 + c + SHIFT) & 63;
    int tok = (b * 64 + gh) * 64 + gw;

    const __half2* qp2 = reinterpret_cast<const __half2*>(
        qkv + (size_t)tok * QKVN + head * DK);
    const __half2* kp2 = qp2 + DIM / 2;
    const __half2* vp2 = qp2 + DIM;

    float qf[DK];
#pragma unroll
    for (int j = 0; j < DK / 2; j++) {
        float2 fq = __half22float2(qp2[j]);
        float2 fk = __half22float2(kp2[j]);
        float2 fv = __half22float2(vp2[j]);
        qf[2 * j] = fq.x;  qf[2 * j + 1] = fq.y;
        Ks[e][2 * j] = fk.x;  Ks[e][2 * j + 1] = fk.y;
        Vs[e][2 * j] = fv.x;  Vs[e][2 * j + 1] = fv.y;
    }
    int ii = wh * 8 + r, jj = wwc * 8 + c;
    int ridi = (ii < HH - WS) ? 0 : ((ii < HH - SHIFT) ? 1 : 2);
    int ridj = (jj < WW_ - WS) ? 0 : ((jj < WW_ - SHIFT) ? 1 : 2);
    cnts[e] = ridi * 3 + ridj;
    for (int t = e; t < TBL; t += 64) tbl[t] = table[t * NHEAD + head];
    __syncthreads();

    const float SCALE = 0.17677669529663687f;  // 1/sqrt(32)
    int mycnt = cnts[e];
    int tb = (r + 7) * 15 + (c + 7);

    // ---- pass 1: scores -> p in shared; only qf[] lives here ---------------
    float sum = 0.f;
#pragma unroll 4
    for (int kk = 0; kk < 64; kk++) {
        const float4* kp4 = reinterpret_cast<const float4*>(Ks[kk]);
        float acc = 0.f;
#pragma unroll
        for (int j = 0; j < DK / 4; j++) {
            float4 k4 = kp4[j];
            acc = fmaf(qf[4 * j],     k4.x, acc);
            acc = fmaf(qf[4 * j + 1], k4.y, acc);
            acc = fmaf(qf[4 * j + 2], k4.z, acc);
            acc = fmaf(qf[4 * j + 3], k4.w, acc);
        }
        int kr = kk >> 3, kc = kk & 7;
        float sc = fmaf(acc, SCALE, tbl[tb - kr * 15 - kc]);
        float p = (mycnt == cnts[kk]) ? __expf(fminf(sc, 80.f)) : 0.f;
        sum += p;
        Ps[e][kk] = p;
    }
    float inv = 1.f / sum;

    // ---- pass 2: weighted V; only o[] lives here ---------------------------
    float o[DK];
#pragma unroll
    for (int j = 0; j < DK; j++) o[j] = 0.f;
#pragma unroll 4
    for (int kk = 0; kk < 64; kk++) {
        float p = Ps[e][kk];
        const float4* vp4 = reinterpret_cast<const float4*>(Vs[kk]);
#pragma unroll
        for (int j = 0; j < DK / 4; j++) {
            float4 v4 = vp4[j];
            o[4 * j]     = fmaf(p, v4.x, o[4 * j]);
            o[4 * j + 1] = fmaf(p, v4.y, o[4 * j + 1]);
            o[4 * j + 2] = fmaf(p, v4.z, o[4 * j + 2]);
            o[4 * j + 3] = fmaf(p, v4.w, o[4 * j + 3]);
        }
    }

    __half2* op2 = reinterpret_cast<__half2*>(
        out + (size_t)tok * DIM + head * DK);
#pragma unroll
    for (int j = 0; j < DK / 2; j++)
        op2[j] = __floats2half2_rn(o[2 * j] * inv, o[2 * j + 1] * inv);
}

// ---------------- launch ----------------------------------------------------
extern "C" void kernel_launch(void* const* d_in, const int* in_sizes, int n_in,
                              void* d_out, int out_size)
{
    const float* x_in  = (const float*)d_in[0];
    const float* Wq   = (const float*)d_in[3];
    const float* bq   = (const float*)d_in[4];
    const float* Wkv  = (const float*)d_in[5];
    const float* bkv  = (const float*)d_in[6];
    const float* Wo   = (const float*)d_in[7];
    const float* bo   = (const float*)d_in[8];
    const float* rtab = (const float*)d_in[9];
    const float* ln1g = (const float*)d_in[10];
    const float* ln1b = (const float*)d_in[11];
    const float* ln2g = (const float*)d_in[12];
    const float* ln2b = (const float*)d_in[13];
    const float* W1   = (const float*)d_in[14];
    const float* b1   = (const float*)d_in[15];
    const float* W2   = (const float*)d_in[16];
    const float* b2   = (const float*)d_in[17];

    float *gx, *gbqkv;
    __half *gxn, *gqkv, *gat, *ghid;
    __half *wqkvT, *woT, *w1T, *w2T;
    cudaGetSymbolAddress((void**)&gx,    g_x);
    cudaGetSymbolAddress((void**)&gxn,   g_xn);
    cudaGetSymbolAddress((void**)&gqkv,  g_qkv);
    cudaGetSymbolAddress((void**)&gat,   g_at);
    cudaGetSymbolAddress((void**)&ghid,  g_h);
    cudaGetSymbolAddress((void**)&wqkvT, g_wqkvT);
    cudaGetSymbolAddress((void**)&gbqkv, g_bqkv);
    cudaGetSymbolAddress((void**)&woT,   g_woT);
    cudaGetSymbolAddress((void**)&w1T,   g_w1T);
    cudaGetSymbolAddress((void**)&w2T,   g_w2T);

    cudaFuncSetAttribute(gemm_tc,
        cudaFuncAttributeMaxDynamicSharedMemorySize, GEMM_SMEM);

    // weight transposes (fp16), batched across layers via gridDim.z
    dim3 tb(32, 8);
    bias_prep<<<LAYERS, 512>>>(bq, bkv, gbqkv);
    // Wq -> wqkvT rows [0,512)
    wt_prep_off<<<dim3(16, 16, LAYERS), tb>>>(
        Wq, wqkvT, DIM, DIM, 0, DIM * DIM, QKVN * DIM);
    // Wkv -> wqkvT rows [512,1536)
    wt_prep_off<<<dim3(32, 16, LAYERS), tb>>>(
        Wkv, wqkvT, DIM, 2 * DIM, DIM, DIM * 2 * DIM, QKVN * DIM);
    wt_prep<<<dim3(16, 16, LAYERS), tb>>>(Wo, woT, DIM, DIM);
    wt_prep<<<dim3(64, 16, LAYERS), tb>>>(W1, w1T, DIM, 4 * DIM);
    wt_prep<<<dim3(16, 64, LAYERS), tb>>>(W2, w2T, 4 * DIM, DIM);

    for (int i = 0; i < LAYERS; i++) {
        const float* cur_x = (i == 0) ? x_in : gx;       // residual stream in
        // LN1
        ln_kernel<<<NTOK, 128>>>(cur_x, ln1g + i * DIM, ln1b + i * DIM, gxn);
        // QKV = xn @ [Wq|Wkv] + [bq|bkv]   (fused, N=1536)
        gemm_tc<<<dim3(QKVN/128, NTOK/128), 256, GEMM_SMEM>>>(
            gxn, wqkvT + (size_t)i*QKVN*DIM, gbqkv + i*QKVN, nullptr, gqkv,
            QKVN, DIM, EPI_BIAS);
        // windowed attention
        attn_kernel<<<dim3(BATCH * 64, NHEAD), 64>>>(
            gqkv, rtab + (size_t)i * TBL * NHEAD, gat);
        // x = res + attn @ Wo + bo
        gemm_tc<<<dim3(DIM/128, NTOK/128), 256, GEMM_SMEM>>>(
            gat, woT + (size_t)i*DIM*DIM, bo + i*DIM, cur_x, gx,
            DIM, DIM, EPI_RES);
        // LN2
        ln_kernel<<<NTOK, 128>>>(gx, ln2g + i * DIM, ln2b + i * DIM, gxn);
        // h = gelu(xn @ W1 + b1)
        gemm_tc<<<dim3(4*DIM/128, NTOK/128), 256, GEMM_SMEM>>>(
            gxn, w1T + (size_t)i*4*DIM*DIM, b1 + i*4*DIM, nullptr, ghid,
            4*DIM, DIM, EPI_GELU);
        // x = x + h @ W2 + b2   (last layer writes d_out directly)
        float* outx = (i == LAYERS - 1) ? (float*)d_out : gx;
        gemm_tc<<<dim3(DIM/128, NTOK/128), 256, GEMM_SMEM>>>(
            ghid, w2T + (size_t)i*DIM*4*DIM, b2 + i*DIM, gx, outx,
            DIM, 4*DIM, EPI_RES);
    }
}

// round 15
// speedup vs baseline: 1.7244x; 1.0403x over previous
#include <cuda_runtime.h>
#include <cuda_fp16.h>
#include <math.h>
#include <stdint.h>

// Problem constants
#define BATCH   8
#define HH      64
#define WW_     64
#define DIM     512
#define NHEAD   16
#define DK      32
#define WS      8
#define SHIFT   4
#define LAYERS  4
#define NTOK    (BATCH * HH * WW_)          // 32768
#define TBL     225                          // (2*WS-1)^2
#define QKVN    (3 * DIM)                    // 1536

// ---------------- scratch (device globals; no allocation allowed) ----------
__device__ float  g_x   [NTOK * DIM];        // running state (f32)
__device__ __half g_xn  [NTOK * DIM];        // layernorm out (fp16)
__device__ __half g_qkv [NTOK * QKVN];       // Q|K|V (fp16)
__device__ __half g_at  [NTOK * DIM];        // attn out (fp16)
__device__ __half g_h   [NTOK * 4 * DIM];    // MLP hidden (fp16)
// transposed fp16 weights, [N, K] row-major
__device__ __half g_wqkvT[LAYERS * QKVN * DIM];   // rows: 0-511 Wq, 512-1535 Wkv
__device__ float  g_bqkv [LAYERS * QKVN];
__device__ __half g_woT [LAYERS * DIM * DIM];
__device__ __half g_w1T [LAYERS * 4 * DIM * DIM];
__device__ __half g_w2T [LAYERS * DIM * 4 * DIM];

// ---------------- helpers ----------------------------------------------------
typedef unsigned long long u64t;

__device__ __forceinline__ uint32_t smem_u32(const void* p) {
    uint32_t a;
    asm("{ .reg .u64 t; cvta.to.shared.u64 t, %1; cvt.u32.u64 %0, t; }"
        : "=r"(a) : "l"(p));
    return a;
}

__device__ __forceinline__ void mma_f16(
    float* c, const uint32_t* a, uint32_t b0, uint32_t b1)
{
    asm volatile(
        "mma.sync.aligned.m16n8k16.row.col.f32.f16.f16.f32 "
        "{%0,%1,%2,%3}, {%4,%5,%6,%7}, {%8,%9}, {%0,%1,%2,%3};\n"
        : "+f"(c[0]), "+f"(c[1]), "+f"(c[2]), "+f"(c[3])
        : "r"(a[0]), "r"(a[1]), "r"(a[2]), "r"(a[3]), "r"(b0), "r"(b1));
}

__device__ __forceinline__ void ldmx4(uint32_t* r, uint32_t addr) {
    asm volatile(
        "ldmatrix.sync.aligned.m8n8.x4.shared.b16 {%0,%1,%2,%3}, [%4];"
        : "=r"(r[0]), "=r"(r[1]), "=r"(r[2]), "=r"(r[3]) : "r"(addr));
}

// packed fp32x2 (Blackwell sm_100+ base ISA; 2x FFMA throughput)
__device__ __forceinline__ u64t pk2(float x, float y) {
    u64t r; asm("mov.b64 %0, {%1, %2};" : "=l"(r) : "f"(x), "f"(y)); return r;
}
__device__ __forceinline__ void upk2(u64t v, float& x, float& y) {
    asm("mov.b64 {%0, %1}, %2;" : "=f"(x), "=f"(y) : "l"(v));
}
__device__ __forceinline__ u64t fma2(u64t a, u64t b, u64t c) {
    u64t d;
    asm("fma.rn.f32x2 %0, %1, %2, %3;" : "=l"(d) : "l"(a), "l"(b), "l"(c));
    return d;
}

// ---------------- weight transpose + fp16 convert ----------------------------
// in: W [K, N] f32 row-major -> out: Wt [N, K] fp16; z = layer index.
__global__ __launch_bounds__(256) void wt_prep(
    const float* __restrict__ W0, __half* __restrict__ Wt0, int K, int N)
{
    const float* W  = W0  + (size_t)blockIdx.z * K * N;
    __half*      Wt = Wt0 + (size_t)blockIdx.z * K * N;
    __shared__ float t[32][33];
    int n0 = blockIdx.x * 32, k0 = blockIdx.y * 32;
    int tx = threadIdx.x, ty = threadIdx.y;   // 32 x 8
#pragma unroll
    for (int i = 0; i < 4; i++)
        t[ty + i * 8][tx] = W[(size_t)(k0 + ty + i * 8) * N + n0 + tx];
    __syncthreads();
#pragma unroll
    for (int i = 0; i < 4; i++)
        Wt[(size_t)(n0 + ty + i * 8) * K + k0 + tx] =
            __float2half_rn(t[tx][ty + i * 8]);
}

// qkv fused weight prep: write Wq rows [0,512) and Wkv rows [512,1536)
__global__ __launch_bounds__(256) void wt_prep_off(
    const float* __restrict__ W0, __half* __restrict__ Wt0, int K, int N,
    int rowOff, int strideW, int strideWt)
{
    const float* W  = W0  + (size_t)blockIdx.z * strideW;
    __half*      Wt = Wt0 + (size_t)blockIdx.z * strideWt + (size_t)rowOff * K;
    __shared__ float t[32][33];
    int n0 = blockIdx.x * 32, k0 = blockIdx.y * 32;
    int tx = threadIdx.x, ty = threadIdx.y;
#pragma unroll
    for (int i = 0; i < 4; i++)
        t[ty + i * 8][tx] = W[(size_t)(k0 + ty + i * 8) * N + n0 + tx];
    __syncthreads();
#pragma unroll
    for (int i = 0; i < 4; i++)
        Wt[(size_t)(n0 + ty + i * 8) * K + k0 + tx] =
            __float2half_rn(t[tx][ty + i * 8]);
}

// concat bq|bkv per layer into g_bqkv
__global__ void bias_prep(const float* __restrict__ bq,
                          const float* __restrict__ bkv,
                          float* __restrict__ out)
{
    int l = blockIdx.x;
    for (int j = threadIdx.x; j < QKVN; j += blockDim.x)
        out[l * QKVN + j] = (j < DIM) ? bq[l * DIM + j]
                                      : bkv[l * 2 * DIM + (j - DIM)];
}

// ---------------- LayerNorm (fp16 output) ------------------------------------
__global__ __launch_bounds__(128) void ln_kernel(
    const float* __restrict__ x, const float* __restrict__ g,
    const float* __restrict__ b, __half* __restrict__ y)
{
    int tok = blockIdx.x;
    const float4* xp = reinterpret_cast<const float4*>(x + (size_t)tok * DIM);
    int tid = threadIdx.x;

    float4 v = xp[tid];
    float s = v.x + v.y + v.z + v.w;

    __shared__ float red1[4], red2[4];
#pragma unroll
    for (int o = 16; o > 0; o >>= 1) s += __shfl_xor_sync(0xffffffffu, s, o);
    if ((tid & 31) == 0) red1[tid >> 5] = s;
    __syncthreads();
    float mean = (red1[0] + red1[1] + red1[2] + red1[3]) * (1.f / DIM);

    float dx = v.x - mean, dy = v.y - mean, dz = v.z - mean, dw = v.w - mean;
    float s2 = dx * dx + dy * dy + dz * dz + dw * dw;
#pragma unroll
    for (int o = 16; o > 0; o >>= 1) s2 += __shfl_xor_sync(0xffffffffu, s2, o);
    if ((tid & 31) == 0) red2[tid >> 5] = s2;
    __syncthreads();
    float var  = (red2[0] + red2[1] + red2[2] + red2[3]) * (1.f / DIM);
    float rstd = rsqrtf(var + 1e-5f);

    int c = tid * 4;
    float4 gg = reinterpret_cast<const float4*>(g)[tid];
    float4 bb = reinterpret_cast<const float4*>(b)[tid];
    float r0 = dx * rstd * gg.x + bb.x;
    float r1 = dy * rstd * gg.y + bb.y;
    float r2 = dz * rstd * gg.z + bb.z;
    float r3 = dw * rstd * gg.w + bb.w;
    __half2* yp2 = reinterpret_cast<__half2*>(y + (size_t)tok * DIM + c);
    yp2[0] = __floats2half2_rn(r0, r1);
    yp2[1] = __floats2half2_rn(r2, r3);
}

// ---------------- tensor-core fp16 GEMM --------------------------------------
// C[M,N] = A[M,K] @ Wt[N,K]^T + bias; epi: bias(fp16) / res-add(f32) / gelu(fp16)
// CTA 128x128, BK=64, 256 threads (8 warps, warp tile 32x64), 3-stage cp.async,
// 2 CTAs/SM so one CTA's mainloop hides the other's prologue/epilogue.
#define EPI_BIAS 0
#define EPI_RES  1
#define EPI_GELU 2

#define RSB    144                              // smem row stride bytes (64h + pad)
#define ATILE  (128 * RSB)                      // 18432 B
#define STAGEB (2 * ATILE)                      // 36864 B (A + B)
#define GEMM_SMEM (3 * STAGEB)                  // 110592 B

__global__ __launch_bounds__(256, 2) void gemm_tc(
    const __half* __restrict__ A, const __half* __restrict__ Wt,
    const float* __restrict__ bias, const float* __restrict__ res,
    void* __restrict__ outP, int N, int K, int epi)
{
    extern __shared__ char smem[];
    uint32_t sbase = smem_u32(smem);

    int tid = threadIdx.x;
    int wid = tid >> 5, lane = tid & 31;
    int gq = lane >> 2, tq = lane & 3;
    int wm = wid >> 1, wn = wid & 1;           // warp: rows wm*32, cols wn*64
    int bn = blockIdx.x * 128, bm = blockIdx.y * 128;

    // ldmatrix lane offsets (bytes within stage)
    int t8 = lane >> 3, l8 = lane & 7;
    uint32_t a_off = (uint32_t)((wm * 32 + (t8 & 1) * 8 + l8) * RSB
                                + (t8 >> 1) * 16);
    uint32_t b_off = (uint32_t)(ATILE + (wn * 64 + (t8 >> 1) * 8 + l8) * RSB
                                + (t8 & 1) * 16);

    float acc[2][8][4];
#pragma unroll
    for (int mt = 0; mt < 2; mt++)
#pragma unroll
        for (int nt = 0; nt < 8; nt++)
#pragma unroll
            for (int r = 0; r < 4; r++) acc[mt][nt][r] = 0.f;

    const int NKB = K >> 6;                     // BK = 64

    // loader: A 128 rows x 8 chunks(16B), B 128 rows x 8 chunks; 256 threads
    int l_row = tid >> 3, l_c = tid & 7;        // base row 0..31, chunk 0..7

#define LOAD_STAGE(kb, stg) do {                                               \
    uint32_t sS = sbase + (uint32_t)(stg) * STAGEB;                            \
    const __half* gA = A  + (size_t)(bm + l_row) * K + (kb) * 64 + l_c * 8;    \
    const __half* gB = Wt + (size_t)(bn + l_row) * K + (kb) * 64 + l_c * 8;    \
    uint32_t dof = (uint32_t)(l_row * RSB + l_c * 16);                         \
    _Pragma("unroll")                                                          \
    for (int i = 0; i < 4; i++)                                                \
        asm volatile("cp.async.cg.shared.global [%0], [%1], 16;"               \
            :: "r"(sS + dof + i * 32 * RSB), "l"(gA + (size_t)i * 32 * K));    \
    _Pragma("unroll")                                                          \
    for (int i = 0; i < 4; i++)                                                \
        asm volatile("cp.async.cg.shared.global [%0], [%1], 16;"               \
            :: "r"(sS + ATILE + dof + i * 32 * RSB),                           \
               "l"(gB + (size_t)i * 32 * K));                                  \
} while (0)

    LOAD_STAGE(0, 0);
    asm volatile("cp.async.commit_group;");
    LOAD_STAGE(1, 1);
    asm volatile("cp.async.commit_group;");

    int stg = 0;
    for (int kb = 0; kb < NKB; kb++) {
        if (kb == NKB - 1) asm volatile("cp.async.wait_group 0;");
        else               asm volatile("cp.async.wait_group 1;");
        __syncthreads();
        if (kb + 2 < NKB) {
            int ns = stg + 2; if (ns >= 3) ns -= 3;
            LOAD_STAGE(kb + 2, ns);
            asm volatile("cp.async.commit_group;");
        }
        uint32_t sS = sbase + (uint32_t)stg * STAGEB;
#pragma unroll
        for (int ks = 0; ks < 4; ks++) {
            uint32_t af[2][4];
            ldmx4(af[0], sS + a_off + ks * 32);
            ldmx4(af[1], sS + a_off + ks * 32 + 16 * RSB);
            uint32_t bf[4][4];
#pragma unroll
            for (int p = 0; p < 4; p++)
                ldmx4(bf[p], sS + b_off + ks * 32 + p * 16 * RSB);
#pragma unroll
            for (int p = 0; p < 4; p++) {
                mma_f16(acc[0][2 * p],     af[0], bf[p][0], bf[p][1]);
                mma_f16(acc[1][2 * p],     af[1], bf[p][0], bf[p][1]);
                mma_f16(acc[0][2 * p + 1], af[0], bf[p][2], bf[p][3]);
                mma_f16(acc[1][2 * p + 1], af[1], bf[p][2], bf[p][3]);
            }
        }
        if (++stg == 3) stg = 0;
    }

    // ---- epilogue ----------------------------------------------------------
    float*  outF = reinterpret_cast<float*>(outP);
    __half* outH = reinterpret_cast<__half*>(outP);
#pragma unroll
    for (int mt = 0; mt < 2; mt++) {
        int row0 = bm + wm * 32 + mt * 16 + gq;
        int row1 = row0 + 8;
#pragma unroll
        for (int nt = 0; nt < 8; nt++) {
            int col = bn + wn * 64 + nt * 8 + 2 * tq;
            float2 bc = *reinterpret_cast<const float2*>(bias + col);
            float v00 = acc[mt][nt][0] + bc.x;
            float v01 = acc[mt][nt][1] + bc.y;
            float v10 = acc[mt][nt][2] + bc.x;
            float v11 = acc[mt][nt][3] + bc.y;
            if (epi == EPI_RES) {
                float2 r0 = *reinterpret_cast<const float2*>(
                    res + (size_t)row0 * N + col);
                float2 r1 = *reinterpret_cast<const float2*>(
                    res + (size_t)row1 * N + col);
                *reinterpret_cast<float2*>(outF + (size_t)row0 * N + col) =
                    make_float2(v00 + r0.x, v01 + r0.y);
                *reinterpret_cast<float2*>(outF + (size_t)row1 * N + col) =
                    make_float2(v10 + r1.x, v11 + r1.y);
            } else if (epi == EPI_GELU) {
                const float K0 = 0.7978845608028654f, K1 = 0.044715f;
                v00 = 0.5f * v00 * (1.f + tanhf(K0 * (v00 + K1 * v00 * v00 * v00)));
                v01 = 0.5f * v01 * (1.f + tanhf(K0 * (v01 + K1 * v01 * v01 * v01)));
                v10 = 0.5f * v10 * (1.f + tanhf(K0 * (v10 + K1 * v10 * v10 * v10)));
                v11 = 0.5f * v11 * (1.f + tanhf(K0 * (v11 + K1 * v11 * v11 * v11)));
                *reinterpret_cast<__half2*>(outH + (size_t)row0 * N + col) =
                    __floats2half2_rn(v00, v01);
                *reinterpret_cast<__half2*>(outH + (size_t)row1 * N + col) =
                    __floats2half2_rn(v10, v11);
            } else {
                *reinterpret_cast<__half2*>(outH + (size_t)row0 * N + col) =
                    __floats2half2_rn(v00, v01);
                *reinterpret_cast<__half2*>(outH + (size_t)row1 * N + col) =
                    __floats2half2_rn(v10, v11);
            }
        }
    }
}

// ---------------- Windowed attention ------------------------------------------
// Two-pass softmax, p staged in shared; packed f32x2 FMA (2x FFMA throughput,
// bit-identical rounding to scalar fmaf).
__global__ __launch_bounds__(64) void attn_kernel(
    const __half* __restrict__ qkv,
    const float* __restrict__ table, __half* __restrict__ out)
{
    __shared__ __align__(16) float Ks[64][DK];
    __shared__ __align__(16) float Vs[64][DK];
    __shared__ float Ps[64][65];
    __shared__ float tbl[TBL];
    __shared__ int   cnts[64];

    int w    = blockIdx.x;
    int head = blockIdx.y;
    int b  = w >> 6;
    int wi = w & 63;
    int wh = wi >> 3, wwc = wi & 7;
    int e  = threadIdx.x;
    int r  = e >> 3, c = e & 7;

    int gh = (wh * 8 + r + SHIFT) & 63;
    int gw = (wwc * 8 + c + SHIFT) & 63;
    int tok = (b * 64 + gh) * 64 + gw;

    const __half2* qp2 = reinterpret_cast<const __half2*>(
        qkv + (size_t)tok * QKVN + head * DK);
    const __half2* kp2 = qp2 + DIM / 2;
    const __half2* vp2 = qp2 + DIM;

    u64t q2[DK / 2];                      // 16 packed f32x2
#pragma unroll
    for (int j = 0; j < DK / 2; j++) {
        float2 fq = __half22float2(qp2[j]);
        float2 fk = __half22float2(kp2[j]);
        float2 fv = __half22float2(vp2[j]);
        q2[j] = pk2(fq.x, fq.y);
        Ks[e][2 * j] = fk.x;  Ks[e][2 * j + 1] = fk.y;
        Vs[e][2 * j] = fv.x;  Vs[e][2 * j + 1] = fv.y;
    }
    int ii = wh * 8 + r, jj = wwc * 8 + c;
    int ridi = (ii < HH - WS) ? 0 : ((ii < HH - SHIFT) ? 1 : 2);
    int ridj = (jj < WW_ - WS) ? 0 : ((jj < WW_ - SHIFT) ? 1 : 2);
    cnts[e] = ridi * 3 + ridj;
    for (int t = e; t < TBL; t += 64) tbl[t] = table[t * NHEAD + head];
    __syncthreads();

    const float SCALE = 0.17677669529663687f;  // 1/sqrt(32)
    int mycnt = cnts[e];
    int tb = (r + 7) * 15 + (c + 7);

    // ---- pass 1: scores -> p in shared; only q2[] lives here ---------------
    float sum = 0.f;
#pragma unroll 4
    for (int kk = 0; kk < 64; kk++) {
        const ulonglong2* kp4 = reinterpret_cast<const ulonglong2*>(Ks[kk]);
        u64t a0 = 0ull, a1 = 0ull;        // (0.f, 0.f) bit patterns
#pragma unroll
        for (int j = 0; j < DK / 4; j++) {
            ulonglong2 kv = kp4[j];
            a0 = fma2(q2[2 * j],     kv.x, a0);
            a1 = fma2(q2[2 * j + 1], kv.y, a1);
        }
        float x0, y0, x1, y1;
        upk2(a0, x0, y0);
        upk2(a1, x1, y1);
        float acc = (x0 + x1) + (y0 + y1);
        int kr = kk >> 3, kc = kk & 7;
        float sc = fmaf(acc, SCALE, tbl[tb - kr * 15 - kc]);
        float p = (mycnt == cnts[kk]) ? __expf(fminf(sc, 80.f)) : 0.f;
        sum += p;
        Ps[e][kk] = p;
    }
    float inv = 1.f / sum;

    // ---- pass 2: weighted V; only o2[] lives here --------------------------
    u64t o2[DK / 2];
#pragma unroll
    for (int j = 0; j < DK / 2; j++) o2[j] = 0ull;
#pragma unroll 4
    for (int kk = 0; kk < 64; kk++) {
        float p = Ps[e][kk];
        u64t pp = pk2(p, p);
        const ulonglong2* vp4 = reinterpret_cast<const ulonglong2*>(Vs[kk]);
#pragma unroll
        for (int j = 0; j < DK / 4; j++) {
            ulonglong2 vv = vp4[j];
            o2[2 * j]     = fma2(pp, vv.x, o2[2 * j]);
            o2[2 * j + 1] = fma2(pp, vv.y, o2[2 * j + 1]);
        }
    }

    __half2* op2 = reinterpret_cast<__half2*>(
        out + (size_t)tok * DIM + head * DK);
#pragma unroll
    for (int j = 0; j < DK / 2; j++) {
        float ox, oy;
        upk2(o2[j], ox, oy);
        op2[j] = __floats2half2_rn(ox * inv, oy * inv);
    }
}

// ---------------- launch ----------------------------------------------------
extern "C" void kernel_launch(void* const* d_in, const int* in_sizes, int n_in,
                              void* d_out, int out_size)
{
    const float* x_in  = (const float*)d_in[0];
    const float* Wq   = (const float*)d_in[3];
    const float* bq   = (const float*)d_in[4];
    const float* Wkv  = (const float*)d_in[5];
    const float* bkv  = (const float*)d_in[6];
    const float* Wo   = (const float*)d_in[7];
    const float* bo   = (const float*)d_in[8];
    const float* rtab = (const float*)d_in[9];
    const float* ln1g = (const float*)d_in[10];
    const float* ln1b = (const float*)d_in[11];
    const float* ln2g = (const float*)d_in[12];
    const float* ln2b = (const float*)d_in[13];
    const float* W1   = (const float*)d_in[14];
    const float* b1   = (const float*)d_in[15];
    const float* W2   = (const float*)d_in[16];
    const float* b2   = (const float*)d_in[17];

    float *gx, *gbqkv;
    __half *gxn, *gqkv, *gat, *ghid;
    __half *wqkvT, *woT, *w1T, *w2T;
    cudaGetSymbolAddress((void**)&gx,    g_x);
    cudaGetSymbolAddress((void**)&gxn,   g_xn);
    cudaGetSymbolAddress((void**)&gqkv,  g_qkv);
    cudaGetSymbolAddress((void**)&gat,   g_at);
    cudaGetSymbolAddress((void**)&ghid,  g_h);
    cudaGetSymbolAddress((void**)&wqkvT, g_wqkvT);
    cudaGetSymbolAddress((void**)&gbqkv, g_bqkv);
    cudaGetSymbolAddress((void**)&woT,   g_woT);
    cudaGetSymbolAddress((void**)&w1T,   g_w1T);
    cudaGetSymbolAddress((void**)&w2T,   g_w2T);

    cudaFuncSetAttribute(gemm_tc,
        cudaFuncAttributeMaxDynamicSharedMemorySize, GEMM_SMEM);

    // weight transposes (fp16), batched across layers via gridDim.z
    dim3 tb(32, 8);
    bias_prep<<<LAYERS, 512>>>(bq, bkv, gbqkv);
    // Wq -> wqkvT rows [0,512)
    wt_prep_off<<<dim3(16, 16, LAYERS), tb>>>(
        Wq, wqkvT, DIM, DIM, 0, DIM * DIM, QKVN * DIM);
    // Wkv -> wqkvT rows [512,1536)
    wt_prep_off<<<dim3(32, 16, LAYERS), tb>>>(
        Wkv, wqkvT, DIM, 2 * DIM, DIM, DIM * 2 * DIM, QKVN * DIM);
    wt_prep<<<dim3(16, 16, LAYERS), tb>>>(Wo, woT, DIM, DIM);
    wt_prep<<<dim3(64, 16, LAYERS), tb>>>(W1, w1T, DIM, 4 * DIM);
    wt_prep<<<dim3(16, 64, LAYERS), tb>>>(W2, w2T, 4 * DIM, DIM);

    for (int i = 0; i < LAYERS; i++) {
        const float* cur_x = (i == 0) ? x_in : gx;       // residual stream in
        // LN1
        ln_kernel<<<NTOK, 128>>>(cur_x, ln1g + i * DIM, ln1b + i * DIM, gxn);
        // QKV = xn @ [Wq|Wkv] + [bq|bkv]   (fused, N=1536)
        gemm_tc<<<dim3(QKVN/128, NTOK/128), 256, GEMM_SMEM>>>(
            gxn, wqkvT + (size_t)i*QKVN*DIM, gbqkv + i*QKVN, nullptr, gqkv,
            QKVN, DIM, EPI_BIAS);
        // windowed attention
        attn_kernel<<<dim3(BATCH * 64, NHEAD), 64>>>(
            gqkv, rtab + (size_t)i * TBL * NHEAD, gat);
        // x = res + attn @ Wo + bo
        gemm_tc<<<dim3(DIM/128, NTOK/128), 256, GEMM_SMEM>>>(
            gat, woT + (size_t)i*DIM*DIM, bo + i*DIM, cur_x, gx,
            DIM, DIM, EPI_RES);
        // LN2
        ln_kernel<<<NTOK, 128>>>(gx, ln2g + i * DIM, ln2b + i * DIM, gxn);
        // h = gelu(xn @ W1 + b1)
        gemm_tc<<<dim3(4*DIM/128, NTOK/128), 256, GEMM_SMEM>>>(
            gxn, w1T + (size_t)i*4*DIM*DIM, b1 + i*4*DIM, nullptr, ghid,
            4*DIM, DIM, EPI_GELU);
        // x = x + h @ W2 + b2   (last layer writes d_out directly)
        float* outx = (i == LAYERS - 1) ? (float*)d_out : gx;
        gemm_tc<<<dim3(DIM/128, NTOK/128), 256, GEMM_SMEM>>>(
            ghid, w2T + (size_t)i*DIM*4*DIM, b2 + i*DIM, gx, outx,
            DIM, 4*DIM, EPI_RES);
    }
}